// round 15
// baseline (speedup 1.0000x reference)
#include <cuda_runtime.h>
#include <cuda_bf16.h>
#include <cstdint>

#define NNODES 50000
#define NEDGES 600000
#define FDIM   128
#define GRID   296                      // 2 CTAs/SM on 148 SMs (<= resident)
#define NTHREADS (GRID * 256)
#define NCHUNKS (NEDGES / 64)           // 9375 exact
#define NTILES  ((NNODES + 127) / 128)  // 391

// ---------------------------------------------------------------------------
// Device scratch (no allocations allowed)
// ---------------------------------------------------------------------------
__device__ float g_xj[NNODES * FDIM];   // aggregated neighbor features
__device__ int   g_ei_is_i64;           // edge_index dtype flag
// Prepacked per-thread B fragments for m16n8k16 bf16 MMA.
// Layout: [kt (8)][nt (16)][lane (32)] of uint4 {bh0, bh1, bl0, bl1}. 64KB.
__device__ uint4 g_w2frag[8 * 16 * 32];
// Grid barrier state (sense-reversing; replay-safe: flag sampled at entry).
__device__ unsigned g_barcnt[2];
__device__ volatile unsigned g_barflag[2];

__device__ __forceinline__ uint32_t pack2_hi(float a, float b) {
    __nv_bfloat162 h = __floats2bfloat162_rn(a, b);
    return *reinterpret_cast<uint32_t*>(&h);
}
__device__ __forceinline__ uint32_t pack2_lo(float a, float b) {
    float la = a - __bfloat162float(__float2bfloat16(a));
    float lb = b - __bfloat162float(__float2bfloat16(b));
    __nv_bfloat162 h = __floats2bfloat162_rn(la, lb);
    return *reinterpret_cast<uint32_t*>(&h);
}

__device__ __forceinline__ void grid_barrier(int b) {
    __syncthreads();
    if (threadIdx.x == 0) {
        unsigned old = g_barflag[b];
        __threadfence();                       // release phase writes
        if (atomicAdd(&g_barcnt[b], 1u) == GRID - 1) {
            g_barcnt[b] = 0;                   // reset for next replay
            __threadfence();
            g_barflag[b] = old + 1u;           // release everyone
        } else {
            while (g_barflag[b] == old) __nanosleep(64);
        }
    }
    __syncthreads();
    __threadfence();   // acquire; gpu-scope fence invalidates L1D (CCTL.IVALL)
}

__device__ __forceinline__ void mma_bf16(float* c, uint32_t a0, uint32_t a1,
                                         uint32_t a2, uint32_t a3,
                                         uint32_t b0, uint32_t b1) {
    asm volatile(
        "mma.sync.aligned.m16n8k16.row.col.f32.bf16.bf16.f32 "
        "{%0,%1,%2,%3}, {%4,%5,%6,%7}, {%8,%9}, {%0,%1,%2,%3};"
        : "+f"(c[0]), "+f"(c[1]), "+f"(c[2]), "+f"(c[3])
        : "r"(a0), "r"(a1), "r"(a2), "r"(a3), "r"(b0), "r"(b1));
}

// ---------------------------------------------------------------------------
// Monolithic persistent kernel:
//   phase 0: pack W2 -> MMA fragments, probe edge dtype, zero g_xj (stcg)
//   phase 1: scatter-add x[src] -> g_xj[dst] via red.global.add.v4.f32
//   phase 2: C = g_xj @ W2 + bias via bf16x3 mma.sync (A via ldcg)
// ---------------------------------------------------------------------------
__global__ __launch_bounds__(256, 2)
void mono_kernel(const float* __restrict__ x, const void* __restrict__ ei,
                 const float* __restrict__ W2, const float* __restrict__ bias,
                 float* __restrict__ out) {
    const int tid = threadIdx.x;
    const int bid = blockIdx.x;
    const int gid = bid * 256 + tid;
    const int wid = tid >> 5;
    const int lane = tid & 31;

    // ---- Phase 0: W2 fragment pack ----
    if (gid < 4096) {
        int kt = gid >> 9;
        int nt = (gid >> 5) & 15;
        int ln = gid & 31;
        int g = ln >> 2, t = ln & 3;
        int n = nt * 8 + g;
        int kc = kt * 16 + 2 * t;
        float w00 = W2[kc * FDIM + n];
        float w01 = W2[(kc + 1) * FDIM + n];
        float w10 = W2[(kc + 8) * FDIM + n];
        float w11 = W2[(kc + 9) * FDIM + n];
        uint4 f;
        f.x = pack2_hi(w00, w01);
        f.y = pack2_hi(w10, w11);
        f.z = pack2_lo(w00, w01);
        f.w = pack2_lo(w10, w11);
        g_w2frag[gid] = f;
    }
    // dtype probe (real int64 ids all in [0,N); int32-as-int64 is not)
    if (bid == 16 && tid == 0) {
        const long long* p = (const long long*)ei;
        int ok = 1;
#pragma unroll
        for (int i = 0; i < 16; i++) {
            long long v = p[i];
            if (v < 0 || v >= NNODES) ok = 0;
        }
        g_ei_is_i64 = ok;
    }
    // zero accumulator (L2-only stores)
    {
        float4 z = make_float4(0.f, 0.f, 0.f, 0.f);
        for (int i = gid; i < NNODES * FDIM / 4; i += NTHREADS)
            __stcg(reinterpret_cast<float4*>(g_xj) + i, z);
    }

    grid_barrier(0);

    // ---- Phase 1: scatter-add (64-edge chunks staged through smem) ----
    __shared__ int ss[64];
    __shared__ int sd[64];
    const int ei64 = g_ei_is_i64;
    for (int chunk = bid; chunk < NCHUNKS; chunk += GRID) {
        const int base = chunk * 64;
        if (tid < 128) {
            int which = tid >> 6;          // 0 = src, 1 = dst
            int i = tid & 63;
            int e = base + i;
            int v;
            if (ei64) v = (int)((const long long*)ei)[(size_t)which * NEDGES + e];
            else      v = ((const int*)ei)[(size_t)which * NEDGES + e];
            if (which == 0) ss[i] = v; else sd[i] = v;
        }
        __syncthreads();
#pragma unroll
        for (int j = 0; j < 8; j++) {
            int i = wid * 8 + j;
            int s = ss[i], d = sd[i];
            const float4 v = *reinterpret_cast<const float4*>(&x[(size_t)s * FDIM + lane * 4]);
            float* dst = &g_xj[(size_t)d * FDIM + lane * 4];
            asm volatile("red.global.add.v4.f32 [%0], {%1, %2, %3, %4};"
                         :: "l"(dst), "f"(v.x), "f"(v.y), "f"(v.z), "f"(v.w)
                         : "memory");
        }
        __syncthreads();   // smem reused next chunk
    }

    grid_barrier(1);

    // ---- Phase 2: GEMM (tile-strided; A via L2-only loads) ----
    const int g = lane >> 2;      // 0..7
    const int t = lane & 3;       // 0..3
    for (int tile = bid; tile < NTILES; tile += GRID) {
        const int row0 = tile * 128 + wid * 16;
        const int r0 = row0 + g;
        const int r1 = row0 + g + 8;

        float acc[16][4];
#pragma unroll
        for (int nt = 0; nt < 16; nt++)
#pragma unroll
            for (int j = 0; j < 4; j++) acc[nt][j] = 0.f;

        const float2 z2 = make_float2(0.f, 0.f);

#pragma unroll 1
        for (int kt = 0; kt < 8; kt++) {
            const int k0 = kt * 16;
            float2 f0 = z2, f1 = z2, f2 = z2, f3 = z2;
            if (r0 < NNODES) {
                f0 = __ldcg(reinterpret_cast<const float2*>(&g_xj[(size_t)r0 * FDIM + k0 + 2 * t]));
                f2 = __ldcg(reinterpret_cast<const float2*>(&g_xj[(size_t)r0 * FDIM + k0 + 2 * t + 8]));
            }
            if (r1 < NNODES) {
                f1 = __ldcg(reinterpret_cast<const float2*>(&g_xj[(size_t)r1 * FDIM + k0 + 2 * t]));
                f3 = __ldcg(reinterpret_cast<const float2*>(&g_xj[(size_t)r1 * FDIM + k0 + 2 * t + 8]));
            }
            uint32_t ah0 = pack2_hi(f0.x, f0.y), ah1 = pack2_hi(f1.x, f1.y);
            uint32_t ah2 = pack2_hi(f2.x, f2.y), ah3 = pack2_hi(f3.x, f3.y);
            uint32_t al0 = pack2_lo(f0.x, f0.y), al1 = pack2_lo(f1.x, f1.y);
            uint32_t al2 = pack2_lo(f2.x, f2.y), al3 = pack2_lo(f3.x, f3.y);

            const uint4* bp = &g_w2frag[(kt * 16) * 32 + lane];
#pragma unroll
            for (int nt = 0; nt < 16; nt++) {
                uint4 bfrag = bp[nt * 32];   // one LDG.128, L1-resident
                mma_bf16(acc[nt], ah0, ah1, ah2, ah3, bfrag.x, bfrag.y);
                mma_bf16(acc[nt], ah0, ah1, ah2, ah3, bfrag.z, bfrag.w);
                mma_bf16(acc[nt], al0, al1, al2, al3, bfrag.x, bfrag.y);
            }
        }

#pragma unroll
        for (int nt = 0; nt < 16; nt++) {
            const int c = nt * 8 + 2 * t;
            float bx = __ldg(&bias[c]);
            float by = __ldg(&bias[c + 1]);
            if (r0 < NNODES) {
                float2 o = make_float2(acc[nt][0] + bx, acc[nt][1] + by);
                *reinterpret_cast<float2*>(&out[(size_t)r0 * FDIM + c]) = o;
            }
            if (r1 < NNODES) {
                float2 o = make_float2(acc[nt][2] + bx, acc[nt][3] + by);
                *reinterpret_cast<float2*>(&out[(size_t)r1 * FDIM + c]) = o;
            }
        }
    }
}

// ---------------------------------------------------------------------------
// kernel_launch
// Inputs: 0:x, 1:edge_index, 2:edge_weight(u), 3:W1(u), 4:b1(u),
//         5:W2, 6:b2, 7:a(u), 8:b(u).  Output: [N,128] f32
// ---------------------------------------------------------------------------
extern "C" void kernel_launch(void* const* d_in, const int* in_sizes, int n_in,
                              void* d_out, int out_size) {
    const float* x   = (const float*)d_in[0];
    const void*  ei  = d_in[1];
    const float* W2  = (const float*)d_in[5];
    const float* b2  = (const float*)d_in[6];
    float*       out = (float*)d_out;

    mono_kernel<<<GRID, 256>>>(x, ei, W2, b2, out);
}